// round 14
// baseline (speedup 1.0000x reference)
#include <cuda_runtime.h>

#define H 64
#define KCH 24
#define THREADS 256
#define CH_PER_CTA 12
#define NT_MAX (KCH * 25)

// ---------------------------------------------------------------------------
// CTA per (channel-half, batch). Builds a per-pixel CSR of conv taps once,
// then for each of its 12 channels: register-gather per pixel + coalesced
// streaming float4 stores. No smem heatmap, no zero-fill, no readback.
// Channel weights are double-buffered so the next channel's load overlaps
// the current channel's gather.
// ---------------------------------------------------------------------------
__global__ __launch_bounds__(THREADS)
void gauss_csr_kernel(const float* __restrict__ x,
                      const float* __restrict__ weight,
                      const int*  __restrict__ vis_batch,
                      const int*  __restrict__ vis_kps,
                      int n_vis,
                      float* __restrict__ out)
{
    const int b   = blockIdx.y;                 // batch
    const int o0  = blockIdx.x * CH_PER_CTA;    // first channel of this CTA
    const int tid = threadIdx.x;

    __shared__ int   offs[H * H];        // 16KB: counts -> starts -> ends
    __shared__ int   ent[NT_MAX];        // tap entries: widx = k*25+dy*5+dx
    __shared__ float wch[2][NT_MAX];     // double-buffered channel weights
    __shared__ int   csum[THREADS];      // chunk sums for the scan
    __shared__ int   killS[KCH];
    __shared__ int   pxS[KCH], pyS[KCH], actS[KCH];

    // ---- zero per-pixel counts ----
    int4 zi = make_int4(0, 0, 0, 0);
    #pragma unroll
    for (int i = 0; i < 4; i++) ((int4*)offs)[tid + i * THREADS] = zi;
    if (tid < KCH) killS[tid] = 0;
    __syncthreads();

    // ---- vis-kill scan (1KB tables, L2-hot) ----
    for (int i = tid; i < n_vis; i += THREADS)
        if (__ldg(&vis_batch[i]) == b) killS[__ldg(&vis_kps[i])] = 1;
    __syncthreads();

    // ---- coords + torch quirk + invalid masking ----
    if (tid < KCH) {
        float fx = __ldg(&x[((size_t)b * KCH + tid) * 2 + 0]);
        float fy = __ldg(&x[((size_t)b * KCH + tid) * 2 + 1]);
        // match JAX: round(((x+1)*0.5)*(H-1)), banker's rounding
        int cx = (int)rintf(((fx + 1.0f) * 0.5f) * (float)(H - 1));
        int cy = (int)rintf(((fy + 1.0f) * 0.5f) * (float)(H - 1));
        pxS[tid] = cx;  pyS[tid] = cy;
        // invalid -> coords zeroed -> cx==0 -> inactive; quirk: cx != 0
        actS[tid] = ((unsigned)cx < (unsigned)H) && ((unsigned)cy < (unsigned)H)
                    && (cx != 0) && (!killS[tid]);
    }
    __syncthreads();

    // ---- pass 1: count taps per pixel ----
    // lax conv = cross-correlation: out[yk+2-dy, xk+2-dx] += w[o,k,dy,dx]
    for (int it = tid; it < NT_MAX; it += THREADS) {
        int k = it / 25;
        if (actS[k]) {
            int t  = it - k * 25;
            int dy = t / 5;
            int dx = t - dy * 5;
            int yy = pyS[k] + 2 - dy;
            int xx = pxS[k] + 2 - dx;
            if ((unsigned)yy < (unsigned)H && (unsigned)xx < (unsigned)H)
                atomicAdd(&offs[yy * H + xx], 1);
        }
    }
    __syncthreads();

    // ---- exclusive scan over 4096 counts (16 per thread + 256-wide scan) ----
    int4 q0 = ((int4*)offs)[tid * 4 + 0];
    int4 q1 = ((int4*)offs)[tid * 4 + 1];
    int4 q2 = ((int4*)offs)[tid * 4 + 2];
    int4 q3 = ((int4*)offs)[tid * 4 + 3];
    int tot = q0.x + q0.y + q0.z + q0.w + q1.x + q1.y + q1.z + q1.w
            + q2.x + q2.y + q2.z + q2.w + q3.x + q3.y + q3.z + q3.w;
    csum[tid] = tot;
    __syncthreads();
    #pragma unroll
    for (int d = 1; d < THREADS; d <<= 1) {
        int add = (tid >= d) ? csum[tid - d] : 0;
        __syncthreads();
        csum[tid] += add;
        __syncthreads();
    }
    int run = csum[tid] - tot;   // exclusive base for this chunk
    int c;
    c = q0.x; q0.x = run; run += c;  c = q0.y; q0.y = run; run += c;
    c = q0.z; q0.z = run; run += c;  c = q0.w; q0.w = run; run += c;
    c = q1.x; q1.x = run; run += c;  c = q1.y; q1.y = run; run += c;
    c = q1.z; q1.z = run; run += c;  c = q1.w; q1.w = run; run += c;
    c = q2.x; q2.x = run; run += c;  c = q2.y; q2.y = run; run += c;
    c = q2.z; q2.z = run; run += c;  c = q2.w; q2.w = run; run += c;
    c = q3.x; q3.x = run; run += c;  c = q3.y; q3.y = run; run += c;
    c = q3.z; q3.z = run; run += c;  c = q3.w; q3.w = run; run += c;
    ((int4*)offs)[tid * 4 + 0] = q0;
    ((int4*)offs)[tid * 4 + 1] = q1;
    ((int4*)offs)[tid * 4 + 2] = q2;
    ((int4*)offs)[tid * 4 + 3] = q3;
    __syncthreads();

    // ---- pass 2: fill entries (turns starts into ends in-place) ----
    for (int it = tid; it < NT_MAX; it += THREADS) {
        int k = it / 25;
        if (actS[k]) {
            int t  = it - k * 25;
            int dy = t / 5;
            int dx = t - dy * 5;
            int yy = pyS[k] + 2 - dy;
            int xx = pxS[k] + 2 - dx;
            if ((unsigned)yy < (unsigned)H && (unsigned)xx < (unsigned)H) {
                int s = atomicAdd(&offs[yy * H + xx], 1);
                ent[s] = it;                  // it == widx
            }
        }
    }

    // preload first channel's weights into buffer 0 (600 floats = 150 float4)
    if (tid < 150)
        ((float4*)wch[0])[tid] =
            __ldg(&((const float4*)(weight + (size_t)o0 * NT_MAX))[tid]);
    __syncthreads();
    // now: start(p) = (p==0) ? 0 : offs[p-1]; end(p) = offs[p]

    // Thread -> pixels: 4 groups of 4 consecutive px, groups 1024 px apart;
    // each STG.128 is a fully coalesced 512B warp transaction.
    const int R0 = tid >> 4;
    const int c0 = (tid & 15) << 2;

    // ---- per-channel loop: gather + stream out (weights double-buffered) ----
    for (int cc = 0; cc < CH_PER_CTA; cc++) {
        const int o   = o0 + cc;
        const int cur = cc & 1;

        // prefetch next channel's weights into the other buffer
        if (cc + 1 < CH_PER_CTA && tid < 150)
            ((float4*)wch[cur ^ 1])[tid] =
                __ldg(&((const float4*)(weight + (size_t)(o + 1) * NT_MAX))[tid]);

        const float* __restrict__ w = wch[cur];
        float4* __restrict__ dst = (float4*)(out + (((size_t)b * KCH + o) << 12));
        #pragma unroll
        for (int i = 0; i < 4; i++) {
            const int r  = R0 + (i << 4);
            const int p0 = r * H + c0;                 // 4-aligned
            int s = (p0 == 0) ? 0 : offs[p0 - 1];
            int4 E = ((const int4*)offs)[p0 >> 2];     // ends of px p0..p0+3
            float4 a = make_float4(0.f, 0.f, 0.f, 0.f);
            for (int e = s; e < E.w; e++) {
                float v = w[ent[e]];
                a.x += (e <  E.x)              ? v : 0.f;
                a.y += (e >= E.x && e < E.y)   ? v : 0.f;
                a.z += (e >= E.y && e < E.z)   ? v : 0.f;
                a.w += (e >= E.z)              ? v : 0.f;
            }
            __stcs(&dst[(i << 8) + tid], a);
        }
        __syncthreads();   // prefetched buffer ready / gathers done before reuse
    }
}

extern "C" void kernel_launch(void* const* d_in, const int* in_sizes, int n_in,
                              void* d_out, int out_size)
{
    const float* x      = (const float*)d_in[0];
    const float* weight = (const float*)d_in[1];
    const int*   vb     = (const int*)d_in[2];
    const int*   vk     = (const int*)d_in[3];
    float*       out    = (float*)d_out;

    int n_vis = in_sizes[2];
    int B     = in_sizes[0] / (KCH * 2);   // 1024

    dim3 grid(KCH / CH_PER_CTA, B);        // (2, 1024)
    gauss_csr_kernel<<<grid, THREADS>>>(x, weight, vb, vk, n_vis, out);
}

// round 15
// speedup vs baseline: 1.9739x; 1.9739x over previous
#include <cuda_runtime.h>

#define H 64
#define KCH 24
#define THREADS 256
#define CHG 4                      // channels per CTA
#define NW  600                    // weights per channel (24*25)

// ---------------------------------------------------------------------------
// One CTA per (channel-quad, batch). Row-list gather (R7 structure), but the
// 4 channels of the quad share every entry decode: weights are interleaved
// [widx][ch] so one LDS.128 feeds 4 channel accumulators.
// ---------------------------------------------------------------------------
__global__ __launch_bounds__(THREADS)
void gauss_quad_kernel(const float* __restrict__ x,
                       const float* __restrict__ weight,
                       const int*  __restrict__ vis_batch,
                       const int*  __restrict__ vis_kps,
                       int n_vis,
                       float* __restrict__ out)
{
    const int o0  = blockIdx.x * CHG;   // first channel of quad
    const int b   = blockIdx.y;         // batch
    const int tid = threadIdx.x;

    __shared__ float4 wq4[NW];          // interleaved weights: [widx] -> 4 ch (9.6KB)
    __shared__ int    cnt[H];           // taps hitting each output row
    __shared__ int    ent[H * KCH];     // per-row entries: (wb<<8)|xk  (wb=k*25+dy*5)
    __shared__ int    killS[KCH];

    if (tid < H)   cnt[tid]  = 0;
    if (tid < KCH) killS[tid] = 0;
    __syncthreads();

    // vis-kill scan (1KB tables, L2-hot)
    for (int i = tid; i < n_vis; i += THREADS)
        if (__ldg(&vis_batch[i]) == b) killS[__ldg(&vis_kps[i])] = 1;

    // interleaved weight load: wq4[widx] = {w[o0][widx], .., w[o0+3][widx]}
    {
        float* wqf = (float*)wq4;
        for (int i = tid; i < NW * CHG; i += THREADS) {
            int ch   = i & (CHG - 1);
            int widx = i >> 2;
            wqf[i] = __ldg(&weight[(size_t)(o0 + ch) * NW + widx]);
        }
    }
    __syncthreads();

    // coords + torch quirk + invalid masking; build per-row lists.
    // lax conv = cross-correlation: out[yk+2-dy, xk+2-dx] += w[o,k,dy,dx]
    if (tid < KCH) {
        float fx = __ldg(&x[((size_t)b * KCH + tid) * 2 + 0]);
        float fy = __ldg(&x[((size_t)b * KCH + tid) * 2 + 1]);
        // match JAX: round(((x+1)*0.5)*(H-1)), banker's rounding
        int cx = (int)rintf(((fx + 1.0f) * 0.5f) * (float)(H - 1));
        int cy = (int)rintf(((fy + 1.0f) * 0.5f) * (float)(H - 1));
        // invalid -> coords zeroed -> cx==0 -> inactive; quirk: cx != 0
        bool act = ((unsigned)cx < (unsigned)H) && ((unsigned)cy < (unsigned)H)
                   && (cx != 0) && (!killS[tid]);
        if (act) {
            int wb = tid * 25;
            #pragma unroll
            for (int dy = 0; dy < 5; dy++) {
                int r = cy + 2 - dy;
                if ((unsigned)r < (unsigned)H) {
                    int s = atomicAdd(&cnt[r], 1);
                    ent[r * KCH + s] = ((wb + dy * 5) << 8) | cx;
                }
            }
        }
    }
    __syncthreads();

    // Thread -> pixels: 4 groups of 4 consecutive px (rows R0+16i, cols c0..c0+3);
    // every STG.128 below is a fully coalesced 512B warp transaction.
    const int R0 = tid >> 4;
    const int c0 = (tid & 15) << 2;
    float* const obase = out + (((size_t)b * KCH + o0) << 12);

    #pragma unroll
    for (int i = 0; i < 4; i++) {
        const int r = R0 + (i << 4);
        const int n = cnt[r];
        const int* el = &ent[r * KCH];
        float4 a0 = make_float4(0.f,0.f,0.f,0.f);   // channel o0, cols c0..c0+3
        float4 a1 = make_float4(0.f,0.f,0.f,0.f);   // channel o0+1
        float4 a2 = make_float4(0.f,0.f,0.f,0.f);   // channel o0+2
        float4 a3 = make_float4(0.f,0.f,0.f,0.f);   // channel o0+3
        for (int e = 0; e < n; e++) {
            int v  = el[e];
            int d0 = (v & 255) + 2 - c0;   // dx for col c0; col c0+j uses d0-j
            int wb = v >> 8;
            if ((unsigned)(d0    ) <= 4u) { float4 wv = wq4[wb + d0    ];
                a0.x += wv.x; a1.x += wv.y; a2.x += wv.z; a3.x += wv.w; }
            if ((unsigned)(d0 - 1) <= 4u) { float4 wv = wq4[wb + d0 - 1];
                a0.y += wv.x; a1.y += wv.y; a2.y += wv.z; a3.y += wv.w; }
            if ((unsigned)(d0 - 2) <= 4u) { float4 wv = wq4[wb + d0 - 2];
                a0.z += wv.x; a1.z += wv.y; a2.z += wv.z; a3.z += wv.w; }
            if ((unsigned)(d0 - 3) <= 4u) { float4 wv = wq4[wb + d0 - 3];
                a0.w += wv.x; a1.w += wv.y; a2.w += wv.z; a3.w += wv.w; }
        }
        const int fi = (i << 8) + tid;
        __stcs((float4*)(obase            ) + fi, a0);
        __stcs((float4*)(obase + (1 << 12)) + fi, a1);
        __stcs((float4*)(obase + (2 << 12)) + fi, a2);
        __stcs((float4*)(obase + (3 << 12)) + fi, a3);
    }
}

extern "C" void kernel_launch(void* const* d_in, const int* in_sizes, int n_in,
                              void* d_out, int out_size)
{
    const float* x      = (const float*)d_in[0];
    const float* weight = (const float*)d_in[1];
    const int*   vb     = (const int*)d_in[2];
    const int*   vk     = (const int*)d_in[3];
    float*       out    = (float*)d_out;

    int n_vis = in_sizes[2];
    int B     = in_sizes[0] / (KCH * 2);   // 1024

    dim3 grid(KCH / CHG, B);               // (6, 1024)
    gauss_quad_kernel<<<grid, THREADS>>>(x, weight, vb, vk, n_vis, out);
}